// round 6
// baseline (speedup 1.0000x reference)
#include <cuda_runtime.h>
#include <cstdint>

// Problem constants
#define TT   100
#define BB   256
#define NIN  1024
#define NHID 4096
#define NOUT 512

#define BETA   0.95f
#define THRESH 1.0f

// Split-K hypothesis: cuBLASLt serial split-K chosen by the XLA autotuner for
// the per-timestep M=256 GEMMs. GEMM1 (256x4096x1024): 64 tiles -> S=2.
// GEMM2 (256x512x4096): 8 tiles -> S=16.
#define SPLIT1 2
#define SPLIT2 16

// Scratch (allocation-free rule: __device__ globals)
__device__ float g_cur1[(size_t)TT * BB * NHID];        // 419 MB
__device__ float g_spk1[(size_t)TT * BB * NHID];        // 419 MB
__device__ float g_cur2[(size_t)TT * BB * NOUT];        //  52 MB
// Partial buffer: max(S1*M*NHID, S2*M*NOUT) = max(2,16)*25600*... = 209,715,200 floats
__device__ float g_part[(size_t)16 * TT * BB * NOUT];   // 839 MB (16*25600*512 == 2*25600*4096)

// ---------------------------------------------------------------------------
// Partial SGEMM (NT): Part[s][M][N] = A[M, ks..ks+Kc) @ B[N, ks..ks+Kc)^T
// s = blockIdx.z, ks = s*Kc. Per element: single fp32 accumulator, ascending-k
// FFMA chain starting from 0 (matches a cuBLAS split-K partial).
// 128x128 tile, BK=16, 256 threads, 8x8 micro-tile. No bias here.
// ---------------------------------------------------------------------------
__global__ __launch_bounds__(256, 2)
void sgemm_nt_part(const float* __restrict__ A,
                   const float* __restrict__ Bm,
                   float* __restrict__ Part,
                   int M, int N, int K, int Kc)
{
    constexpr int BM = 128, BN = 128, BK = 16;
    __shared__ float As[BK][BM + 4];
    __shared__ float Bs[BK][BN + 4];

    const int tid = threadIdx.x;
    const int bm  = blockIdx.y * BM;
    const int bn  = blockIdx.x * BN;
    const int s   = blockIdx.z;
    const int kb  = s * Kc;
    const int tx  = tid & 15;
    const int ty  = tid >> 4;

    const int lRow = tid >> 2;        // 0..63
    const int lC4  = (tid & 3) << 2;  // 0,4,8,12

    const float* Aptr = A  + (size_t)bm * K + kb;
    const float* Bptr = Bm + (size_t)bn * K + kb;

    float acc[8][8];
#pragma unroll
    for (int i = 0; i < 8; i++)
#pragma unroll
        for (int j = 0; j < 8; j++) acc[i][j] = 0.0f;

    for (int k0 = 0; k0 < Kc; k0 += BK) {
#pragma unroll
        for (int r = 0; r < 2; r++) {
            const int row = lRow + r * 64;
            float4 va = *(const float4*)(Aptr + (size_t)row * K + k0 + lC4);
            As[lC4 + 0][row] = va.x;
            As[lC4 + 1][row] = va.y;
            As[lC4 + 2][row] = va.z;
            As[lC4 + 3][row] = va.w;
            float4 vb = *(const float4*)(Bptr + (size_t)row * K + k0 + lC4);
            Bs[lC4 + 0][row] = vb.x;
            Bs[lC4 + 1][row] = vb.y;
            Bs[lC4 + 2][row] = vb.z;
            Bs[lC4 + 3][row] = vb.w;
        }
        __syncthreads();

#pragma unroll
        for (int k = 0; k < BK; k++) {
            float a[8], b[8];
            *(float4*)(a)     = *(const float4*)&As[k][ty * 8];
            *(float4*)(a + 4) = *(const float4*)&As[k][ty * 8 + 4];
            *(float4*)(b)     = *(const float4*)&Bs[k][tx * 8];
            *(float4*)(b + 4) = *(const float4*)&Bs[k][tx * 8 + 4];
#pragma unroll
            for (int i = 0; i < 8; i++)
#pragma unroll
                for (int j = 0; j < 8; j++)
                    acc[i][j] = __fmaf_rn(a[i], b[j], acc[i][j]);
        }
        __syncthreads();
    }

    float* base = Part + (size_t)s * M * N;
#pragma unroll
    for (int i = 0; i < 8; i++) {
        const int row = bm + ty * 8 + i;
        float* outp = base + (size_t)row * N + bn + tx * 8;
        *(float4*)(outp)     = make_float4(acc[i][0], acc[i][1], acc[i][2], acc[i][3]);
        *(float4*)(outp + 4) = make_float4(acc[i][4], acc[i][5], acc[i][6], acc[i][7]);
    }
}

// ---------------------------------------------------------------------------
// Split-K reduce: C[m,n] = ((P0 + P1) + ... + P_{S-1}) + bias[n]
// Each add separately rounded, ascending split order (serial split-K reduce),
// bias last (cuBLASLt epilogue / XLA broadcast-add).
// ---------------------------------------------------------------------------
__global__ void reduce_splitk_bias(const float* __restrict__ Part,
                                   const float* __restrict__ bias,
                                   float* __restrict__ C,
                                   int MN, int N, int S)
{
    const int idx = blockIdx.x * blockDim.x + threadIdx.x;
    if (idx >= MN) return;
    float t = Part[idx];
    for (int s = 1; s < S; s++)
        t = __fadd_rn(t, Part[(size_t)s * MN + idx]);
    C[idx] = __fadd_rn(t, bias[idx % N]);
}

// ---------------------------------------------------------------------------
// LIF recurrences: XLA fused elementwise ops are separately rounded:
//   t = 0.95*mem; t = t + cur; t = t - rst  (rst*1.0 simplified away)
// ---------------------------------------------------------------------------
__device__ __forceinline__ float lif_update(float mem, float c) {
    const float rst = (mem > THRESH) ? THRESH : 0.0f;
    float t = __fmul_rn(BETA, mem);
    t = __fadd_rn(t, c);
    t = __fsub_rn(t, rst);
    return t;
}

__global__ void lif_scan1(const float* __restrict__ cur1,
                          float* __restrict__ spk1)
{
    const int idx = blockIdx.x * blockDim.x + threadIdx.x;
    if (idx >= BB * NHID) return;
    const size_t stride = (size_t)BB * NHID;
    size_t off = idx;
    float mem = 0.0f;
#pragma unroll 4
    for (int t = 0; t < TT; t++) {
        mem = lif_update(mem, cur1[off]);
        spk1[off] = (mem > THRESH) ? 1.0f : 0.0f;
        off += stride;
    }
}

__global__ void lif_scan2(const float* __restrict__ cur2,
                          float* __restrict__ out)
{
    const int idx = blockIdx.x * blockDim.x + threadIdx.x;
    if (idx >= BB * NOUT) return;
    const size_t stride = (size_t)BB * NOUT;
    const size_t half   = (size_t)TT * BB * NOUT;
    size_t off = idx;
    float mem = 0.0f;
#pragma unroll 4
    for (int t = 0; t < TT; t++) {
        mem = lif_update(mem, cur2[off]);
        out[off]        = (mem > THRESH) ? 1.0f : 0.0f;  // spk_rec
        out[half + off] = mem;                           // mem_rec
        off += stride;
    }
}

// ---------------------------------------------------------------------------
// Launch
// ---------------------------------------------------------------------------
extern "C" void kernel_launch(void* const* d_in, const int* in_sizes, int n_in,
                              void* d_out, int out_size)
{
    const float* x  = (const float*)d_in[0];   // [T,B,NIN]
    const float* W1 = (const float*)d_in[1];   // [NHID,NIN]
    const float* b1 = (const float*)d_in[2];   // [NHID]
    const float* W2 = (const float*)d_in[3];   // [NOUT,NHID]
    const float* b2 = (const float*)d_in[4];   // [NOUT]
    float* out = (float*)d_out;

    float* cur1; cudaGetSymbolAddress((void**)&cur1, g_cur1);
    float* spk1; cudaGetSymbolAddress((void**)&spk1, g_spk1);
    float* cur2; cudaGetSymbolAddress((void**)&cur2, g_cur2);
    float* part; cudaGetSymbolAddress((void**)&part, g_part);

    const int M = TT * BB;  // 25600

    // GEMM1 partials: split-K = 2 over K=1024 (chunks of 512)
    {
        dim3 grid(NHID / 128, M / 128, SPLIT1);
        sgemm_nt_part<<<grid, 256>>>(x, W1, part, M, NHID, NIN, NIN / SPLIT1);
        const int MN = M * NHID;
        reduce_splitk_bias<<<(MN + 255) / 256, 256>>>(part, b1, cur1, MN, NHID, SPLIT1);
    }

    // LIF scan layer 1 -> spike train
    {
        const int n = BB * NHID;
        lif_scan1<<<(n + 255) / 256, 256>>>(cur1, spk1);
    }

    // GEMM2 partials: split-K = 16 over K=4096 (chunks of 256)
    {
        dim3 grid(NOUT / 128, M / 128, SPLIT2);
        sgemm_nt_part<<<grid, 256>>>(spk1, W2, part, M, NOUT, NHID, NHID / SPLIT2);
        const int MN = M * NOUT;
        reduce_splitk_bias<<<(MN + 255) / 256, 256>>>(part, b2, cur2, MN, NOUT, SPLIT2);
    }

    // LIF scan layer 2 -> d_out (spk_rec || mem_rec)
    {
        const int n = BB * NOUT;
        lif_scan2<<<(n + 255) / 256, 256>>>(cur2, out);
    }
}

// round 8
// speedup vs baseline: 1.1984x; 1.1984x over previous
#include <cuda_runtime.h>
#include <cstdint>

// Problem constants
#define TT   100
#define BB   256
#define NIN  1024
#define NHID 4096
#define NOUT 512

#define BETA   0.95f
#define THRESH 1.0f

// Confirmed reference arithmetic: cuBLASLt serial split-K.
// GEMM1 (per-step 256x4096x1024): S=2.  GEMM2 (256x512x4096): S=16.
#define SPLIT1 2
#define SPLIT2 16

// Scratch (allocation-free rule: __device__ globals)
__device__ float g_spk1[(size_t)TT * BB * NHID];        // 419 MB
// Partial buffer: 2*M*NHID == 16*M*NOUT == 209,715,200 floats (839 MB)
__device__ float g_part[(size_t)16 * TT * BB * NOUT];

// ---------------------------------------------------------------------------
// Partial SGEMM (NT): Part[s][M][N] = A[M, ks..ks+Kc) @ B[N, ks..ks+Kc)^T
// s = blockIdx.z, ks = s*Kc.
// BM=256 x BN=128 tile, BK=16, 256 threads, 16x8 micro-tile per thread.
// Double-buffered smem, register-staged global loads.
// PAD = +4 floats so each k-row stride is a multiple of 16 BYTES -> float4
// smem loads stay aligned (the +2 pad in the previous round trapped).
// NUMERICS: per output element, a single fp32 accumulator folded by an
// ascending-k FFMA chain starting from 0 — identical to the passing kernel.
// ---------------------------------------------------------------------------
#define BM 256
#define BN 128
#define BK 16
#define LDA (BM + 4)
#define LDB (BN + 4)
#define GEMM_SMEM ((size_t)2 * BK * (LDA + LDB) * sizeof(float))

__global__ __launch_bounds__(256, 1)
void sgemm_nt_part(const float* __restrict__ A,
                   const float* __restrict__ Bm,
                   float* __restrict__ Part,
                   int M, int N, int K, int Kc)
{
    extern __shared__ float sm[];
    float (*As)[BK][LDA] = (float (*)[BK][LDA])sm;
    float (*Bs)[BK][LDB] = (float (*)[BK][LDB])(sm + 2 * BK * LDA);

    const int tid  = threadIdx.x;
    const int bm   = blockIdx.y * BM;
    const int bn   = blockIdx.x * BN;
    const int s    = blockIdx.z;
    const int kb   = s * Kc;

    const int warp = tid >> 5;
    const int lane = tid & 31;
    // warp grid: 2 warps along M (128 rows each), 4 warps along N (32 cols)
    const int m0 = (warp & 1) * 128 + (lane >> 2) * 16;
    const int n0 = (warp >> 1) * 32 + (lane & 3) * 8;

    // global->smem loader mapping
    const int lr = tid >> 2;          // base row 0..63
    const int c4 = (tid & 3) * 4;     // k-offset 0,4,8,12

    const float* Ap = A  + (size_t)bm * K + kb;
    const float* Bp = Bm + (size_t)bn * K + kb;

    float acc[16][8];
#pragma unroll
    for (int i = 0; i < 16; i++)
#pragma unroll
        for (int j = 0; j < 8; j++) acc[i][j] = 0.0f;

    const int NT = Kc / BK;
    float4 ar[4], br[2];

    // ---- prologue: tile 0 ----
#pragma unroll
    for (int i = 0; i < 4; i++)
        ar[i] = *(const float4*)(Ap + (size_t)(lr + i * 64) * K + c4);
#pragma unroll
    for (int i = 0; i < 2; i++)
        br[i] = *(const float4*)(Bp + (size_t)(lr + i * 64) * K + c4);
#pragma unroll
    for (int i = 0; i < 4; i++) {
        const int r = lr + i * 64;
        As[0][c4 + 0][r] = ar[i].x; As[0][c4 + 1][r] = ar[i].y;
        As[0][c4 + 2][r] = ar[i].z; As[0][c4 + 3][r] = ar[i].w;
    }
#pragma unroll
    for (int i = 0; i < 2; i++) {
        const int r = lr + i * 64;
        Bs[0][c4 + 0][r] = br[i].x; Bs[0][c4 + 1][r] = br[i].y;
        Bs[0][c4 + 2][r] = br[i].z; Bs[0][c4 + 3][r] = br[i].w;
    }
    __syncthreads();

    for (int kt = 0; kt < NT; kt++) {
        const int cur = kt & 1;

        // prefetch next tile into registers (LDG hidden under compute)
        if (kt + 1 < NT) {
            const int k0 = (kt + 1) * BK;
#pragma unroll
            for (int i = 0; i < 4; i++)
                ar[i] = *(const float4*)(Ap + (size_t)(lr + i * 64) * K + k0 + c4);
#pragma unroll
            for (int i = 0; i < 2; i++)
                br[i] = *(const float4*)(Bp + (size_t)(lr + i * 64) * K + k0 + c4);
        }

        // compute: ascending k within the tile (chain order preserved)
#pragma unroll
        for (int k = 0; k < BK; k++) {
            float a[16], b[8];
#pragma unroll
            for (int i = 0; i < 4; i++)
                *(float4*)(a + i * 4) = *(const float4*)&As[cur][k][m0 + i * 4];
            *(float4*)(b)     = *(const float4*)&Bs[cur][k][n0];
            *(float4*)(b + 4) = *(const float4*)&Bs[cur][k][n0 + 4];
#pragma unroll
            for (int i = 0; i < 16; i++)
#pragma unroll
                for (int j = 0; j < 8; j++)
                    acc[i][j] = __fmaf_rn(a[i], b[j], acc[i][j]);
        }

        if (kt + 1 < NT) {
            const int nxt = cur ^ 1;
#pragma unroll
            for (int i = 0; i < 4; i++) {
                const int r = lr + i * 64;
                As[nxt][c4 + 0][r] = ar[i].x; As[nxt][c4 + 1][r] = ar[i].y;
                As[nxt][c4 + 2][r] = ar[i].z; As[nxt][c4 + 3][r] = ar[i].w;
            }
#pragma unroll
            for (int i = 0; i < 2; i++) {
                const int r = lr + i * 64;
                Bs[nxt][c4 + 0][r] = br[i].x; Bs[nxt][c4 + 1][r] = br[i].y;
                Bs[nxt][c4 + 2][r] = br[i].z; Bs[nxt][c4 + 3][r] = br[i].w;
            }
            __syncthreads();
        }
    }

    // epilogue: raw partials (no bias here — reduce+bias fused into LIF)
    float* base = Part + (size_t)s * M * N + (size_t)(bm + m0) * N + bn + n0;
#pragma unroll
    for (int i = 0; i < 16; i++) {
        *(float4*)(base + (size_t)i * N)     =
            make_float4(acc[i][0], acc[i][1], acc[i][2], acc[i][3]);
        *(float4*)(base + (size_t)i * N + 4) =
            make_float4(acc[i][4], acc[i][5], acc[i][6], acc[i][7]);
    }
}

// ---------------------------------------------------------------------------
// LIF scans with fused split-K reduce + bias.
// Reduce: t = p0; t = t + p1; ... (ascending s, each add rounded); c = t + bias.
// LIF: u = 0.95*mem; u = u + c; mem = u - rst  (separately rounded ops).
// Identical rounding sequence to the passing two-kernel version.
// ---------------------------------------------------------------------------
__global__ void lif_scan1(const float* __restrict__ part,
                          const float* __restrict__ bias,
                          float* __restrict__ spk1)
{
    const int idx = blockIdx.x * blockDim.x + threadIdx.x;
    if (idx >= BB * NHID) return;
    const size_t stride  = (size_t)BB * NHID;
    const size_t pstride = (size_t)TT * BB * NHID;  // split stride
    const float  bv = bias[idx % NHID];
    size_t off = idx;
    float mem = 0.0f;
#pragma unroll 4
    for (int t = 0; t < TT; t++) {
        float c = __fadd_rn(part[off], part[pstride + off]);
        c = __fadd_rn(c, bv);
        const float rst = (mem > THRESH) ? THRESH : 0.0f;
        float u = __fmul_rn(BETA, mem);
        u = __fadd_rn(u, c);
        mem = __fsub_rn(u, rst);
        spk1[off] = (mem > THRESH) ? 1.0f : 0.0f;
        off += stride;
    }
}

__global__ void lif_scan2(const float* __restrict__ part,
                          const float* __restrict__ bias,
                          float* __restrict__ out)
{
    const int idx = blockIdx.x * blockDim.x + threadIdx.x;
    if (idx >= BB * NOUT) return;
    const size_t stride  = (size_t)BB * NOUT;
    const size_t pstride = (size_t)TT * BB * NOUT;
    const size_t half    = (size_t)TT * BB * NOUT;
    const float  bv = bias[idx % NOUT];
    size_t off = idx;
    float mem = 0.0f;
    for (int t = 0; t < TT; t++) {
        float c = part[off];
#pragma unroll
        for (int s = 1; s < SPLIT2; s++)
            c = __fadd_rn(c, part[(size_t)s * pstride + off]);
        c = __fadd_rn(c, bv);
        const float rst = (mem > THRESH) ? THRESH : 0.0f;
        float u = __fmul_rn(BETA, mem);
        u = __fadd_rn(u, c);
        mem = __fsub_rn(u, rst);
        out[off]        = (mem > THRESH) ? 1.0f : 0.0f;  // spk_rec
        out[half + off] = mem;                           // mem_rec
        off += stride;
    }
}

// ---------------------------------------------------------------------------
// Launch
// ---------------------------------------------------------------------------
extern "C" void kernel_launch(void* const* d_in, const int* in_sizes, int n_in,
                              void* d_out, int out_size)
{
    const float* x  = (const float*)d_in[0];   // [T,B,NIN]
    const float* W1 = (const float*)d_in[1];   // [NHID,NIN]
    const float* b1 = (const float*)d_in[2];   // [NHID]
    const float* W2 = (const float*)d_in[3];   // [NOUT,NHID]
    const float* b2 = (const float*)d_in[4];   // [NOUT]
    float* out = (float*)d_out;

    float* spk1; cudaGetSymbolAddress((void**)&spk1, g_spk1);
    float* part; cudaGetSymbolAddress((void**)&part, g_part);

    // opt-in smem (idempotent host-side attribute set; capture-safe)
    cudaFuncSetAttribute(sgemm_nt_part,
                         cudaFuncAttributeMaxDynamicSharedMemorySize,
                         (int)GEMM_SMEM);

    const int M = TT * BB;  // 25600

    // GEMM1 partials: split-K = 2 over K=1024 (chunks of 512)
    {
        dim3 grid(NHID / BN, M / BM, SPLIT1);
        sgemm_nt_part<<<grid, 256, GEMM_SMEM>>>(x, W1, part, M, NHID, NIN, NIN / SPLIT1);
    }

    // LIF scan layer 1 (fused split-K reduce + bias) -> spike train
    {
        const int n = BB * NHID;
        lif_scan1<<<(n + 255) / 256, 256>>>(part, b1, spk1);
    }

    // GEMM2 partials: split-K = 16 over K=4096 (chunks of 256)
    {
        dim3 grid(NOUT / BN, M / BM, SPLIT2);
        sgemm_nt_part<<<grid, 256, GEMM_SMEM>>>(spk1, W2, part, M, NOUT, NHID, NHID / SPLIT2);
    }

    // LIF scan layer 2 (fused reduce + bias) -> d_out (spk_rec || mem_rec)
    {
        const int n = BB * NOUT;
        lif_scan2<<<(n + 255) / 256, 256>>>(part, b2, out);
    }
}